// round 15
// baseline (speedup 1.0000x reference)
#include <cuda_runtime.h>
#include <cuda_fp16.h>

#define BATCH 4
#define CIN   96
#define DI    192
#define HH    128
#define WW    128
#define HWSZ  16384
#define KDIR  4

// ---------------- scratch ----------------
__device__ __half g_t1[(size_t)BATCH*DI*HWSZ];                // in_proj output (B,D,HW) fp16
__device__ __half g_xft[(size_t)BATCH*HWSZ*DI];               // conv+silu, transposed (B,HW,D) fp16
__device__ float  g_xdbl[(size_t)BATCH*HWSZ*32];              // (B,HW,K*8) spatial order
__device__ __half g_ys[(size_t)BATCH*HWSZ*KDIR*DI];           // (B,HW,K,D) spatial order, fp16
__device__ __half g_g[(size_t)BATCH*HWSZ*DI];                 // gelu(sum_k ys) (B,HW,D) fp16

// ---------------- f32x2 packed helpers ----------------
__device__ __forceinline__ unsigned long long pk2(float x, float y) {
    unsigned long long r;
    asm("mov.b64 %0, {%1, %2};" : "=l"(r) : "f"(x), "f"(y));
    return r;
}
__device__ __forceinline__ void upk2(float& lo, float& hi, unsigned long long v) {
    asm("mov.b64 {%0, %1}, %2;" : "=f"(lo), "=f"(hi) : "l"(v));
}
#define FMA2(d, a, b) asm("fma.rn.f32x2 %0, %1, %2, %0;" : "+l"(d) : "l"(a), "l"(b))

// =====================================================================
// K1: in_proj, outputs split in half per block.
// grid (HW/64, 2, B), block 256.  smem ~64KB.  t1 stored fp16.
// =====================================================================
__global__ void __launch_bounds__(256) k1_inproj(const float* __restrict__ x,
                                                 const float* __restrict__ w) {
    extern __shared__ float sm1[];
    float* sw = sm1;              // sw[c*98 + olocal]
    float* sx = sm1 + 96*98;      // sx[c*68 + t]
    int b = blockIdx.z, oh = blockIdx.y;
    int pos0 = blockIdx.x * 64;
    int tid = threadIdx.x;

    for (int i = tid; i < 96*96; i += 256)
        sw[(i % 96)*98 + (i / 96)] = w[oh*96*96 + (i/96)*96 + (i%96)];
    for (int i = tid; i < CIN*64; i += 256) {
        int c = i >> 6, t = i & 63;
        sx[c*68 + t] = x[((size_t)b*CIN + c)*HWSZ + pos0 + t];
    }
    __syncthreads();

    int tg = tid & 15, og = tid >> 4;
    int t0 = tg * 4, o0 = og * 6;
    unsigned long long acc[3][4];
    #pragma unroll
    for (int i = 0; i < 3; i++)
        #pragma unroll
        for (int j = 0; j < 4; j++) acc[i][j] = 0ull;

    for (int c = 0; c < CIN; ++c) {
        float4 xv = *(const float4*)&sx[c*68 + t0];
        unsigned long long xp[4] = {pk2(xv.x, xv.x), pk2(xv.y, xv.y),
                                    pk2(xv.z, xv.z), pk2(xv.w, xv.w)};
        const float* wrow = &sw[c*98 + o0];
        #pragma unroll
        for (int i = 0; i < 3; ++i) {
            unsigned long long wp = *(const unsigned long long*)&wrow[2*i];
            #pragma unroll
            for (int t = 0; t < 4; ++t) FMA2(acc[i][t], wp, xp[t]);
        }
    }
    #pragma unroll
    for (int i = 0; i < 3; ++i) {
        float lo[4], hi[4];
        #pragma unroll
        for (int t = 0; t < 4; ++t) upk2(lo[t], hi[t], acc[i][t]);
        size_t r0 = ((size_t)b*DI + oh*96 + o0 + 2*i)*HWSZ + pos0 + t0;
        *(__half2*)&g_t1[r0]            = __floats2half2_rn(lo[0], lo[1]);
        *(__half2*)&g_t1[r0 + 2]        = __floats2half2_rn(lo[2], lo[3]);
        *(__half2*)&g_t1[r0 + HWSZ]     = __floats2half2_rn(hi[0], hi[1]);
        *(__half2*)&g_t1[r0 + HWSZ + 2] = __floats2half2_rn(hi[2], hi[3]);
    }
}

// =====================================================================
// K2 (fused): depthwise 3x3 conv + bias + silu -> xft (transposed, fp16)
//             AND x_dbl projection (xpw staged in dead s_in).
// grid (W/32, H, B), block 256.  smem ~111KB, 2 blocks/SM.
// Halo load vectorized: aligned half2 pairs (c=1..32), edge cols scalar.
// =====================================================================
__global__ void __launch_bounds__(256) k2_conv(const float* __restrict__ cw,
                                               const float* __restrict__ cb,
                                               const float* __restrict__ xpw) {
    extern __shared__ float sm2[];
    float* s_in  = sm2;                 // [rc*193 + d], rc = r*34+c
    float* s_out = sm2 + 102*193;       // [w*193 + d]
    float* s_w9  = sm2 + 102*193 + 32*193;   // [d*9+i]
    float* s_b   = s_w9 + DI*9;              // [d]
    float* s_xw  = s_in;                      // reused after conv: [d*36 + kc]
    int b = blockIdx.z, h = blockIdx.y, w0 = blockIdx.x * 32;
    int tid = threadIdx.x;

    for (int i = tid; i < DI*9; i += 256) s_w9[i] = cw[i];
    for (int i = tid; i < DI; i += 256) s_b[i] = cb[i];
    // halo load: per (dd, r): item 0 = c0 scalar, items 1..16 = half2 pairs
    // (c = 2*it-1, 2*it), item 17 = c33 scalar.  54 items per dd.
    for (int i = tid; i < 54*DI; i += 256) {
        int dd = i / 54, q = i % 54;
        int r = q / 18, it = q % 18;
        int hh = h + r - 1;
        const __half* row = g_t1 + ((size_t)b*DI + dd)*HWSZ + hh*WW;
        if (it == 0) {
            int ww = w0 - 1;
            float v = 0.f;
            if (hh >= 0 && hh < HH && ww >= 0)
                v = __half2float(row[ww]);
            s_in[(r*34)*193 + dd] = v;
        } else if (it == 17) {
            int ww = w0 + 32;
            float v = 0.f;
            if (hh >= 0 && hh < HH && ww < WW)
                v = __half2float(row[ww]);
            s_in[(r*34 + 33)*193 + dd] = v;
        } else {
            int c1 = 2*it - 1;              // 1..31 odd
            int ww = w0 + c1 - 1;           // even, in [w0, w0+30]: always valid
            float2 v = make_float2(0.f, 0.f);
            if (hh >= 0 && hh < HH)
                v = __half22float2(*(const __half2*)(row + ww));
            s_in[(r*34 + c1)*193 + dd]     = v.x;
            s_in[(r*34 + c1 + 1)*193 + dd] = v.y;
        }
    }
    __syncthreads();

    int w = tid & 31, dg = tid >> 5;
    #pragma unroll 4
    for (int dd = 0; dd < 24; ++dd) {
        int d = dg*24 + dd;
        float sum = s_b[d];
        #pragma unroll
        for (int r = 0; r < 3; ++r)
            #pragma unroll
            for (int dc = 0; dc < 3; ++dc)
                sum += s_w9[d*9 + r*3 + dc] * s_in[(r*34 + w + dc)*193 + d];
        s_out[w*193 + d] = sum / (1.f + __expf(-sum));
    }
    __syncthreads();        // s_out complete; s_in now dead

    for (int i = tid; i < 32*DI; i += 256) {
        int ww = i / DI, d = i % DI;
        g_xft[((size_t)b*HWSZ + h*WW + w0 + ww)*DI + d] = __float2half_rn(s_out[ww*193 + d]);
    }
    for (int i = tid; i < 32*DI; i += 256) {
        int kc = i / DI, d2 = i % DI;
        s_xw[d2*36 + kc] = xpw[i];
    }
    __syncthreads();

    int og = tid >> 5;                  // 8 groups of 4 kc
    unsigned long long acc2[2] = {0ull, 0ull};
    for (int d = 0; d < DI; ++d) {
        float s = s_out[w*193 + d];
        unsigned long long sp = pk2(s, s);
        const float* xw = &s_xw[d*36 + og*4];
        unsigned long long w01 = *(const unsigned long long*)&xw[0];
        unsigned long long w23 = *(const unsigned long long*)&xw[2];
        FMA2(acc2[0], w01, sp);
        FMA2(acc2[1], w23, sp);
    }
    float r0, r1, r2, r3;
    upk2(r0, r1, acc2[0]);
    upk2(r2, r3, acc2[1]);
    size_t pos = (size_t)b*HWSZ + h*WW + w0 + w;
    *(float4*)&g_xdbl[pos*32 + og*4] = make_float4(r0, r1, r2, r3);
}

// =====================================================================
// K4: selective scan (R13 version — frozen).
// block 256 = 32 slots x 8 d; warp w scans channel d=w via shfl.
// grid (DI/8=24, K, B) = 384 blocks.  ys fp16, u fp16.
// =====================================================================
__global__ void __launch_bounds__(256, 4) k4_scan(const float* __restrict__ dtw,
                        const float* __restrict__ dtb,
                        const float* __restrict__ Alog,
                        const float* __restrict__ Dsv,
                        const int*   __restrict__ scan) {
    __shared__ float s_pa[32*9], s_pb[32*9], s_hs[32*9];
    int b = blockIdx.z, k = blockIdx.y, dg = blockIdx.x;
    int tid = threadIdx.x;
    int dsub = tid & 7, slot = tid >> 3;
    int d = dg*8 + dsub;
    int kd = k*DI + d;
    int lane = tid & 31, wid = tid >> 5;

    float w0 = dtw[kd*6+0], w1 = dtw[kd*6+1], w2 = dtw[kd*6+2];
    float w3 = dtw[kd*6+3], w4 = dtw[kd*6+4], w5 = dtw[kd*6+5];
    float bias = dtb[kd];
    float Aval = -__expf(Alog[kd]);
    float Dval = Dsv[kd];
    const int*    sc     = scan + k*HWSZ;
    const float*  xdbl_b = g_xdbl + (size_t)b*HWSZ*32 + k*8;
    const __half* xft_b  = g_xft  + (size_t)b*HWSZ*DI + d;
    __half*       ys_b   = g_ys   + (size_t)b*HWSZ*(KDIR*DI) + k*DI + d;
    float hprev = 0.f;

    for (int ch = 0; ch < 64; ++ch) {
        int l0 = ch*256 + slot*8;
        int4 pA = *(const int4*)&sc[l0];
        int4 pB = *(const int4*)&sc[l0 + 4];
        int pos[8] = {pA.x, pA.y, pA.z, pA.w, pB.x, pB.y, pB.z, pB.w};

        float a[8], bu[8], Cv[8], du[8];
        #pragma unroll
        for (int j = 0; j < 8; ++j) {
            const float4* xb = (const float4*)(xdbl_b + (size_t)pos[j]*32);
            float4 q1 = xb[0];
            float4 q2 = xb[1];
            float u = __half2float(xft_b[(size_t)pos[j]*DI]);
            float dt = bias + w0*q1.x + w1*q1.y + w2*q1.z + w3*q1.w + w4*q2.x + w5*q2.y;
            float delta = fmaxf(dt, 0.f) + __logf(1.f + __expf(-fabsf(dt)));
            a[j]  = __expf(delta * Aval);
            bu[j] = delta * q2.z * u;
            Cv[j] = q2.w;
            du[j] = Dval * u;
        }
        float aP = a[0], bP = bu[0];
        #pragma unroll
        for (int j = 1; j < 8; ++j) { bP = a[j]*bP + bu[j]; aP *= a[j]; }
        s_pa[slot*9 + dsub] = aP;
        s_pb[slot*9 + dsub] = bP;
        __syncthreads();

        {   // warp `wid` scans the 32 slot-partials of channel dsub==wid
            float ai = s_pa[lane*9 + wid];
            float bi = s_pb[lane*9 + wid];
            #pragma unroll
            for (int off = 1; off < 32; off <<= 1) {
                float pa = __shfl_up_sync(0xffffffffu, ai, off);
                float pb = __shfl_up_sync(0xffffffffu, bi, off);
                if (lane >= off) { bi = ai*pb + bi; ai *= pa; }
            }
            float aE = __shfl_up_sync(0xffffffffu, ai, 1);
            float bE = __shfl_up_sync(0xffffffffu, bi, 1);
            if (lane == 0) { aE = 1.f; bE = 0.f; }
            s_hs[lane*9 + wid] = aE*hprev + bE;
            float aI = __shfl_sync(0xffffffffu, ai, 31);
            float bI = __shfl_sync(0xffffffffu, bi, 31);
            hprev = aI*hprev + bI;
        }
        __syncthreads();

        float h = s_hs[slot*9 + dsub];
        #pragma unroll
        for (int j = 0; j < 8; ++j) {
            h = a[j]*h + bu[j];
            ys_b[(size_t)pos[j]*(KDIR*DI)] = __float2half_rn(Cv[j]*h + du[j]);
        }
    }
}

// =====================================================================
// K5a: streaming sum over K + gelu, 16B loads/stores.
// block 192 = 24 q x 8 po; grid B*HW/8.  Thread q handles 8 d.
// =====================================================================
__global__ void __launch_bounds__(192) k5a_gelu(void) {
    int tid = threadIdx.x;
    int q = tid % 24, po = tid / 24;
    size_t pg = (size_t)blockIdx.x*8 + po;
    const uint4* src = (const uint4*)(g_ys + pg*(KDIR*DI));   // 16B = 8 halfs
    float acc[8];
    {
        uint4 v = src[q];
        const __half2* h2 = (const __half2*)&v;
        #pragma unroll
        for (int p = 0; p < 4; ++p) {
            float2 f = __half22float2(h2[p]);
            acc[2*p] = f.x; acc[2*p+1] = f.y;
        }
    }
    #pragma unroll
    for (int kk = 1; kk < KDIR; ++kk) {
        uint4 v = src[kk*24 + q];
        const __half2* h2 = (const __half2*)&v;
        #pragma unroll
        for (int p = 0; p < 4; ++p) {
            float2 f = __half22float2(h2[p]);
            acc[2*p] += f.x; acc[2*p+1] += f.y;
        }
    }
    uint4 outv;
    __half2* oh2 = (__half2*)&outv;
    #pragma unroll
    for (int p = 0; p < 4; ++p) {
        float r0 = acc[2*p], r1 = acc[2*p+1];
        float z0 = 0.7978845608f * (r0 + 0.044715f*r0*r0*r0);
        float z1 = 0.7978845608f * (r1 + 0.044715f*r1*r1*r1);
        float t0 = 2.f / (1.f + __expf(-2.f*z0)) - 1.f;
        float t1 = 2.f / (1.f + __expf(-2.f*z1)) - 1.f;
        oh2[p] = __floats2half2_rn(0.5f*r0*(1.f + t0), 0.5f*r1*(1.f + t1));
    }
    ((uint4*)(g_g + pg*DI))[q] = outv;
}

// =====================================================================
// K5b: out_proj GEMM, outputs split 2-way.  grid (HW/64, 2, B), block 256
// g loaded as half2.
// =====================================================================
__global__ void __launch_bounds__(256) k5b_out(const float* __restrict__ ow,
                                               float* __restrict__ out) {
    extern __shared__ float sm5[];
    float* sw = sm5;              // sw[d*50 + ol]
    float* sg = sm5 + DI*50;      // sg[d*70 + t]
    int b = blockIdx.z, oq = blockIdx.y;
    int pos0 = blockIdx.x * 64, tid = threadIdx.x;

    for (int i = tid; i < 48*DI; i += 256)
        sw[(i % DI)*50 + (i / DI)] = ow[oq*48*DI + i];
    int lane = tid & 31, wid = tid >> 5;
    #pragma unroll
    for (int pp = 0; pp < 8; ++pp) {
        int po = wid*8 + pp;
        const __half2* src = (const __half2*)(g_g + ((size_t)b*HWSZ + pos0 + po)*DI);
        #pragma unroll
        for (int i = 0; i < 3; ++i) {
            int d2 = lane + 32*i;                 // half2 index, d = 2*d2
            float2 v = __half22float2(src[d2]);
            sg[(2*d2)*70 + po]     = v.x;
            sg[(2*d2 + 1)*70 + po] = v.y;
        }
    }
    __syncthreads();

    int tg = tid & 31, og = tid >> 5;
    int t0 = tg*2, o0 = og*6;
    unsigned long long acc[3][2];
    #pragma unroll
    for (int i = 0; i < 3; i++) { acc[i][0] = 0ull; acc[i][1] = 0ull; }

    for (int d = 0; d < DI; ++d) {
        float2 gv = *(const float2*)&sg[d*70 + t0];
        unsigned long long gp[2] = {pk2(gv.x, gv.x), pk2(gv.y, gv.y)};
        const float* wrow = &sw[d*50 + o0];
        #pragma unroll
        for (int i = 0; i < 3; ++i) {
            unsigned long long wp = *(const unsigned long long*)&wrow[2*i];
            FMA2(acc[i][0], wp, gp[0]);
            FMA2(acc[i][1], wp, gp[1]);
        }
    }
    #pragma unroll
    for (int i = 0; i < 3; ++i) {
        float lo0, hi0, lo1, hi1;
        upk2(lo0, hi0, acc[i][0]);
        upk2(lo1, hi1, acc[i][1]);
        size_t r0 = ((size_t)b*CIN + oq*48 + o0 + 2*i)*HWSZ + pos0 + t0;
        *(float2*)&out[r0]        = make_float2(lo0, lo1);
        *(float2*)&out[r0 + HWSZ] = make_float2(hi0, hi1);
    }
}

// =====================================================================
extern "C" void kernel_launch(void* const* d_in, const int* in_sizes, int n_in,
                              void* d_out, int out_size) {
    const float* x    = (const float*)d_in[0];
    const int*   scan = (const int*)d_in[1];
    const float* ipw  = (const float*)d_in[3];
    const float* cw   = (const float*)d_in[4];
    const float* cb   = (const float*)d_in[5];
    const float* xpw  = (const float*)d_in[6];
    const float* dtw  = (const float*)d_in[7];
    const float* dtb  = (const float*)d_in[8];
    const float* Alog = (const float*)d_in[9];
    const float* Dsv  = (const float*)d_in[10];
    const float* ow   = (const float*)d_in[11];
    float* out = (float*)d_out;

    const int SM1 = (96*98 + 96*68) * 4;
    const int SM2 = (102*193 + 32*193 + DI*9 + DI) * 4;
    const int SM5 = (DI*50 + DI*70) * 4;
    cudaFuncSetAttribute(k1_inproj, cudaFuncAttributeMaxDynamicSharedMemorySize, SM1);
    cudaFuncSetAttribute(k2_conv,   cudaFuncAttributeMaxDynamicSharedMemorySize, SM2);
    cudaFuncSetAttribute(k5b_out,   cudaFuncAttributeMaxDynamicSharedMemorySize, SM5);

    dim3 g1(HWSZ/64, 2, BATCH);
    k1_inproj<<<g1, 256, SM1>>>(x, ipw);
    dim3 g2(WW/32, HH, BATCH);
    k2_conv<<<g2, 256, SM2>>>(cw, cb, xpw);
    dim3 g4(DI/8, KDIR, BATCH);
    k4_scan<<<g4, 256>>>(dtw, dtb, Alog, Dsv, scan);
    k5a_gelu<<<BATCH*HWSZ/8, 192>>>();
    dim3 g5(HWSZ/64, 2, BATCH);
    k5b_out<<<g5, 256, SM5>>>(ow, out);
}

// round 16
// speedup vs baseline: 1.2305x; 1.2305x over previous
#include <cuda_runtime.h>
#include <cuda_fp16.h>

#define BATCH 4
#define CIN   96
#define DI    192
#define HH    128
#define WW    128
#define HWSZ  16384
#define KDIR  4

// ---------------- scratch ----------------
__device__ __half g_t1[(size_t)BATCH*DI*HWSZ];                // in_proj output (B,D,HW) fp16
__device__ __half g_xft[(size_t)BATCH*HWSZ*DI];               // conv+silu, transposed (B,HW,D) fp16
__device__ float  g_xdbl[(size_t)BATCH*HWSZ*32];              // (B,HW,K*8) spatial order
__device__ __half g_ys[(size_t)BATCH*HWSZ*KDIR*DI];           // (B,HW,K,D) spatial order, fp16
__device__ __half g_g[(size_t)BATCH*HWSZ*DI];                 // gelu(sum_k ys) (B,HW,D) fp16

// ---------------- f32x2 packed helpers ----------------
__device__ __forceinline__ unsigned long long pk2(float x, float y) {
    unsigned long long r;
    asm("mov.b64 %0, {%1, %2};" : "=l"(r) : "f"(x), "f"(y));
    return r;
}
__device__ __forceinline__ void upk2(float& lo, float& hi, unsigned long long v) {
    asm("mov.b64 {%0, %1}, %2;" : "=f"(lo), "=f"(hi) : "l"(v));
}
#define FMA2(d, a, b) asm("fma.rn.f32x2 %0, %1, %2, %0;" : "+l"(d) : "l"(a), "l"(b))

// =====================================================================
// K1: in_proj, outputs split in half per block.
// grid (HW/64, 2, B), block 256.  smem ~64KB.  t1 stored fp16.
// =====================================================================
__global__ void __launch_bounds__(256) k1_inproj(const float* __restrict__ x,
                                                 const float* __restrict__ w) {
    extern __shared__ float sm1[];
    float* sw = sm1;              // sw[c*98 + olocal]
    float* sx = sm1 + 96*98;      // sx[c*68 + t]
    int b = blockIdx.z, oh = blockIdx.y;
    int pos0 = blockIdx.x * 64;
    int tid = threadIdx.x;

    for (int i = tid; i < 96*96; i += 256)
        sw[(i % 96)*98 + (i / 96)] = w[oh*96*96 + (i/96)*96 + (i%96)];
    for (int i = tid; i < CIN*64; i += 256) {
        int c = i >> 6, t = i & 63;
        sx[c*68 + t] = x[((size_t)b*CIN + c)*HWSZ + pos0 + t];
    }
    __syncthreads();

    int tg = tid & 15, og = tid >> 4;
    int t0 = tg * 4, o0 = og * 6;
    unsigned long long acc[3][4];
    #pragma unroll
    for (int i = 0; i < 3; i++)
        #pragma unroll
        for (int j = 0; j < 4; j++) acc[i][j] = 0ull;

    for (int c = 0; c < CIN; ++c) {
        float4 xv = *(const float4*)&sx[c*68 + t0];
        unsigned long long xp[4] = {pk2(xv.x, xv.x), pk2(xv.y, xv.y),
                                    pk2(xv.z, xv.z), pk2(xv.w, xv.w)};
        const float* wrow = &sw[c*98 + o0];
        #pragma unroll
        for (int i = 0; i < 3; ++i) {
            unsigned long long wp = *(const unsigned long long*)&wrow[2*i];
            #pragma unroll
            for (int t = 0; t < 4; ++t) FMA2(acc[i][t], wp, xp[t]);
        }
    }
    #pragma unroll
    for (int i = 0; i < 3; ++i) {
        float lo[4], hi[4];
        #pragma unroll
        for (int t = 0; t < 4; ++t) upk2(lo[t], hi[t], acc[i][t]);
        size_t r0 = ((size_t)b*DI + oh*96 + o0 + 2*i)*HWSZ + pos0 + t0;
        *(__half2*)&g_t1[r0]            = __floats2half2_rn(lo[0], lo[1]);
        *(__half2*)&g_t1[r0 + 2]        = __floats2half2_rn(lo[2], lo[3]);
        *(__half2*)&g_t1[r0 + HWSZ]     = __floats2half2_rn(hi[0], hi[1]);
        *(__half2*)&g_t1[r0 + HWSZ + 2] = __floats2half2_rn(hi[2], hi[3]);
    }
}

// =====================================================================
// K2 (fused): depthwise 3x3 conv + bias + silu -> xft (transposed, fp16)
//             AND x_dbl projection (xpw staged in dead s_in).  (R13 version)
// grid (W/32, H, B), block 256.  smem ~111KB, 2 blocks/SM.
// =====================================================================
__global__ void __launch_bounds__(256) k2_conv(const float* __restrict__ cw,
                                               const float* __restrict__ cb,
                                               const float* __restrict__ xpw) {
    extern __shared__ float sm2[];
    float* s_in  = sm2;                 // [rc*193 + d], rc = r*34+c
    float* s_out = sm2 + 102*193;       // [w*193 + d]
    float* s_w9  = sm2 + 102*193 + 32*193;   // [d*9+i]
    float* s_b   = s_w9 + DI*9;              // [d]
    float* s_xw  = s_in;                      // reused after conv: [d*36 + kc]
    int b = blockIdx.z, h = blockIdx.y, w0 = blockIdx.x * 32;
    int tid = threadIdx.x;

    for (int i = tid; i < DI*9; i += 256) s_w9[i] = cw[i];
    for (int i = tid; i < DI; i += 256) s_b[i] = cb[i];
    for (int i = tid; i < 3*34*DI; i += 256) {
        int dd = i / 102, rc = i % 102;
        int r = rc / 34, c = rc % 34;
        int hh = h + r - 1, ww = w0 + c - 1;
        float v = 0.f;
        if (hh >= 0 && hh < HH && ww >= 0 && ww < WW)
            v = __half2float(g_t1[((size_t)b*DI + dd)*HWSZ + hh*WW + ww]);
        s_in[rc*193 + dd] = v;
    }
    __syncthreads();

    int w = tid & 31, dg = tid >> 5;
    #pragma unroll 4
    for (int dd = 0; dd < 24; ++dd) {
        int d = dg*24 + dd;
        float sum = s_b[d];
        #pragma unroll
        for (int r = 0; r < 3; ++r)
            #pragma unroll
            for (int dc = 0; dc < 3; ++dc)
                sum += s_w9[d*9 + r*3 + dc] * s_in[(r*34 + w + dc)*193 + d];
        s_out[w*193 + d] = sum / (1.f + __expf(-sum));
    }
    __syncthreads();        // s_out complete; s_in now dead

    for (int i = tid; i < 32*DI; i += 256) {
        int ww = i / DI, d = i % DI;
        g_xft[((size_t)b*HWSZ + h*WW + w0 + ww)*DI + d] = __float2half_rn(s_out[ww*193 + d]);
    }
    for (int i = tid; i < 32*DI; i += 256) {
        int kc = i / DI, d2 = i % DI;
        s_xw[d2*36 + kc] = xpw[i];
    }
    __syncthreads();

    int og = tid >> 5;                  // 8 groups of 4 kc
    unsigned long long acc2[2] = {0ull, 0ull};
    for (int d = 0; d < DI; ++d) {
        float s = s_out[w*193 + d];
        unsigned long long sp = pk2(s, s);
        const float* xw = &s_xw[d*36 + og*4];
        unsigned long long w01 = *(const unsigned long long*)&xw[0];
        unsigned long long w23 = *(const unsigned long long*)&xw[2];
        FMA2(acc2[0], w01, sp);
        FMA2(acc2[1], w23, sp);
    }
    float r0, r1, r2, r3;
    upk2(r0, r1, acc2[0]);
    upk2(r2, r3, acc2[1]);
    size_t pos = (size_t)b*HWSZ + h*WW + w0 + w;
    *(float4*)&g_xdbl[pos*32 + og*4] = make_float4(r0, r1, r2, r3);
}

// =====================================================================
// K4: selective scan (frozen).
// block 256 = 32 slots x 8 d; warp w scans channel d=w via shfl.
// grid (DI/8=24, K, B) = 384 blocks.  ys fp16, u fp16.
// =====================================================================
__global__ void __launch_bounds__(256, 4) k4_scan(const float* __restrict__ dtw,
                        const float* __restrict__ dtb,
                        const float* __restrict__ Alog,
                        const float* __restrict__ Dsv,
                        const int*   __restrict__ scan) {
    __shared__ float s_pa[32*9], s_pb[32*9], s_hs[32*9];
    int b = blockIdx.z, k = blockIdx.y, dg = blockIdx.x;
    int tid = threadIdx.x;
    int dsub = tid & 7, slot = tid >> 3;
    int d = dg*8 + dsub;
    int kd = k*DI + d;
    int lane = tid & 31, wid = tid >> 5;

    float w0 = dtw[kd*6+0], w1 = dtw[kd*6+1], w2 = dtw[kd*6+2];
    float w3 = dtw[kd*6+3], w4 = dtw[kd*6+4], w5 = dtw[kd*6+5];
    float bias = dtb[kd];
    float Aval = -__expf(Alog[kd]);
    float Dval = Dsv[kd];
    const int*    sc     = scan + k*HWSZ;
    const float*  xdbl_b = g_xdbl + (size_t)b*HWSZ*32 + k*8;
    const __half* xft_b  = g_xft  + (size_t)b*HWSZ*DI + d;
    __half*       ys_b   = g_ys   + (size_t)b*HWSZ*(KDIR*DI) + k*DI + d;
    float hprev = 0.f;

    for (int ch = 0; ch < 64; ++ch) {
        int l0 = ch*256 + slot*8;
        int4 pA = *(const int4*)&sc[l0];
        int4 pB = *(const int4*)&sc[l0 + 4];
        int pos[8] = {pA.x, pA.y, pA.z, pA.w, pB.x, pB.y, pB.z, pB.w};

        float a[8], bu[8], Cv[8], du[8];
        #pragma unroll
        for (int j = 0; j < 8; ++j) {
            const float4* xb = (const float4*)(xdbl_b + (size_t)pos[j]*32);
            float4 q1 = xb[0];
            float4 q2 = xb[1];
            float u = __half2float(xft_b[(size_t)pos[j]*DI]);
            float dt = bias + w0*q1.x + w1*q1.y + w2*q1.z + w3*q1.w + w4*q2.x + w5*q2.y;
            float delta = fmaxf(dt, 0.f) + __logf(1.f + __expf(-fabsf(dt)));
            a[j]  = __expf(delta * Aval);
            bu[j] = delta * q2.z * u;
            Cv[j] = q2.w;
            du[j] = Dval * u;
        }
        float aP = a[0], bP = bu[0];
        #pragma unroll
        for (int j = 1; j < 8; ++j) { bP = a[j]*bP + bu[j]; aP *= a[j]; }
        s_pa[slot*9 + dsub] = aP;
        s_pb[slot*9 + dsub] = bP;
        __syncthreads();

        {   // warp `wid` scans the 32 slot-partials of channel dsub==wid
            float ai = s_pa[lane*9 + wid];
            float bi = s_pb[lane*9 + wid];
            #pragma unroll
            for (int off = 1; off < 32; off <<= 1) {
                float pa = __shfl_up_sync(0xffffffffu, ai, off);
                float pb = __shfl_up_sync(0xffffffffu, bi, off);
                if (lane >= off) { bi = ai*pb + bi; ai *= pa; }
            }
            float aE = __shfl_up_sync(0xffffffffu, ai, 1);
            float bE = __shfl_up_sync(0xffffffffu, bi, 1);
            if (lane == 0) { aE = 1.f; bE = 0.f; }
            s_hs[lane*9 + wid] = aE*hprev + bE;
            float aI = __shfl_sync(0xffffffffu, ai, 31);
            float bI = __shfl_sync(0xffffffffu, bi, 31);
            hprev = aI*hprev + bI;
        }
        __syncthreads();

        float h = s_hs[slot*9 + dsub];
        #pragma unroll
        for (int j = 0; j < 8; ++j) {
            h = a[j]*h + bu[j];
            ys_b[(size_t)pos[j]*(KDIR*DI)] = __float2half_rn(Cv[j]*h + du[j]);
        }
    }
}

// =====================================================================
// K5a: streaming sum over K + gelu, 16B loads/stores (kept: measured win).
// block 192 = 24 q x 8 po; grid B*HW/8.  Thread q handles 8 d.
// =====================================================================
__global__ void __launch_bounds__(192) k5a_gelu(void) {
    int tid = threadIdx.x;
    int q = tid % 24, po = tid / 24;
    size_t pg = (size_t)blockIdx.x*8 + po;
    const uint4* src = (const uint4*)(g_ys + pg*(KDIR*DI));   // 16B = 8 halfs
    float acc[8];
    {
        uint4 v = src[q];
        const __half2* h2 = (const __half2*)&v;
        #pragma unroll
        for (int p = 0; p < 4; ++p) {
            float2 f = __half22float2(h2[p]);
            acc[2*p] = f.x; acc[2*p+1] = f.y;
        }
    }
    #pragma unroll
    for (int kk = 1; kk < KDIR; ++kk) {
        uint4 v = src[kk*24 + q];
        const __half2* h2 = (const __half2*)&v;
        #pragma unroll
        for (int p = 0; p < 4; ++p) {
            float2 f = __half22float2(h2[p]);
            acc[2*p] += f.x; acc[2*p+1] += f.y;
        }
    }
    uint4 outv;
    __half2* oh2 = (__half2*)&outv;
    #pragma unroll
    for (int p = 0; p < 4; ++p) {
        float r0 = acc[2*p], r1 = acc[2*p+1];
        float z0 = 0.7978845608f * (r0 + 0.044715f*r0*r0*r0);
        float z1 = 0.7978845608f * (r1 + 0.044715f*r1*r1*r1);
        float t0 = 2.f / (1.f + __expf(-2.f*z0)) - 1.f;
        float t1 = 2.f / (1.f + __expf(-2.f*z1)) - 1.f;
        oh2[p] = __floats2half2_rn(0.5f*r0*(1.f + t0), 0.5f*r1*(1.f + t1));
    }
    ((uint4*)(g_g + pg*DI))[q] = outv;
}

// =====================================================================
// K5b: out_proj GEMM, outputs split 2-way (R13 version).
// grid (HW/64, 2, B), block 256
// =====================================================================
__global__ void __launch_bounds__(256) k5b_out(const float* __restrict__ ow,
                                               float* __restrict__ out) {
    extern __shared__ float sm5[];
    float* sw = sm5;              // sw[d*50 + ol]
    float* sg = sm5 + DI*50;      // sg[d*70 + t]
    int b = blockIdx.z, oq = blockIdx.y;
    int pos0 = blockIdx.x * 64, tid = threadIdx.x;

    for (int i = tid; i < 48*DI; i += 256)
        sw[(i % DI)*50 + (i / DI)] = ow[oq*48*DI + i];
    int lane = tid & 31, wid = tid >> 5;
    #pragma unroll
    for (int pp = 0; pp < 8; ++pp) {
        int po = wid*8 + pp;
        const __half* src = g_g + ((size_t)b*HWSZ + pos0 + po)*DI;
        #pragma unroll
        for (int i = 0; i < 6; ++i)
            sg[(lane + 32*i)*70 + po] = __half2float(src[lane + 32*i]);
    }
    __syncthreads();

    int tg = tid & 31, og = tid >> 5;
    int t0 = tg*2, o0 = og*6;
    unsigned long long acc[3][2];
    #pragma unroll
    for (int i = 0; i < 3; i++) { acc[i][0] = 0ull; acc[i][1] = 0ull; }

    for (int d = 0; d < DI; ++d) {
        float2 gv = *(const float2*)&sg[d*70 + t0];
        unsigned long long gp[2] = {pk2(gv.x, gv.x), pk2(gv.y, gv.y)};
        const float* wrow = &sw[d*50 + o0];
        #pragma unroll
        for (int i = 0; i < 3; ++i) {
            unsigned long long wp = *(const unsigned long long*)&wrow[2*i];
            FMA2(acc[i][0], wp, gp[0]);
            FMA2(acc[i][1], wp, gp[1]);
        }
    }
    #pragma unroll
    for (int i = 0; i < 3; ++i) {
        float lo0, hi0, lo1, hi1;
        upk2(lo0, hi0, acc[i][0]);
        upk2(lo1, hi1, acc[i][1]);
        size_t r0 = ((size_t)b*CIN + oq*48 + o0 + 2*i)*HWSZ + pos0 + t0;
        *(float2*)&out[r0]        = make_float2(lo0, lo1);
        *(float2*)&out[r0 + HWSZ] = make_float2(hi0, hi1);
    }
}

// =====================================================================
extern "C" void kernel_launch(void* const* d_in, const int* in_sizes, int n_in,
                              void* d_out, int out_size) {
    const float* x    = (const float*)d_in[0];
    const int*   scan = (const int*)d_in[1];
    const float* ipw  = (const float*)d_in[3];
    const float* cw   = (const float*)d_in[4];
    const float* cb   = (const float*)d_in[5];
    const float* xpw  = (const float*)d_in[6];
    const float* dtw  = (const float*)d_in[7];
    const float* dtb  = (const float*)d_in[8];
    const float* Alog = (const float*)d_in[9];
    const float* Dsv  = (const float*)d_in[10];
    const float* ow   = (const float*)d_in[11];
    float* out = (float*)d_out;

    const int SM1 = (96*98 + 96*68) * 4;
    const int SM2 = (102*193 + 32*193 + DI*9 + DI) * 4;
    const int SM5 = (DI*50 + DI*70) * 4;
    cudaFuncSetAttribute(k1_inproj, cudaFuncAttributeMaxDynamicSharedMemorySize, SM1);
    cudaFuncSetAttribute(k2_conv,   cudaFuncAttributeMaxDynamicSharedMemorySize, SM2);
    cudaFuncSetAttribute(k5b_out,   cudaFuncAttributeMaxDynamicSharedMemorySize, SM5);

    dim3 g1(HWSZ/64, 2, BATCH);
    k1_inproj<<<g1, 256, SM1>>>(x, ipw);
    dim3 g2(WW/32, HH, BATCH);
    k2_conv<<<g2, 256, SM2>>>(cw, cb, xpw);
    dim3 g4(DI/8, KDIR, BATCH);
    k4_scan<<<g4, 256>>>(dtw, dtb, Alog, Dsv, scan);
    k5a_gelu<<<BATCH*HWSZ/8, 192>>>();
    dim3 g5(HWSZ/64, 2, BATCH);
    k5b_out<<<g5, 256, SM5>>>(ow, out);
}

// round 17
// speedup vs baseline: 1.3002x; 1.0567x over previous
#include <cuda_runtime.h>
#include <cuda_fp16.h>

#define BATCH 4
#define CIN   96
#define DI    192
#define HH    128
#define WW    128
#define HWSZ  16384
#define KDIR  4

// ---------------- scratch ----------------
__device__ __half g_t1[(size_t)BATCH*DI*HWSZ];                // in_proj output (B,D,HW) fp16
__device__ __half g_xft[(size_t)BATCH*HWSZ*DI];               // conv+silu, transposed (B,HW,D) fp16
__device__ __half g_xdbl[(size_t)BATCH*HWSZ*32];              // (B,HW,K*8) spatial order, fp16
__device__ __half g_ys[(size_t)BATCH*HWSZ*KDIR*DI];           // (B,HW,K,D) spatial order, fp16
__device__ __half g_g[(size_t)BATCH*HWSZ*DI];                 // gelu(sum_k ys) (B,HW,D) fp16

// ---------------- f32x2 packed helpers ----------------
__device__ __forceinline__ unsigned long long pk2(float x, float y) {
    unsigned long long r;
    asm("mov.b64 %0, {%1, %2};" : "=l"(r) : "f"(x), "f"(y));
    return r;
}
__device__ __forceinline__ void upk2(float& lo, float& hi, unsigned long long v) {
    asm("mov.b64 {%0, %1}, %2;" : "=f"(lo), "=f"(hi) : "l"(v));
}
#define FMA2(d, a, b) asm("fma.rn.f32x2 %0, %1, %2, %0;" : "+l"(d) : "l"(a), "l"(b))

// =====================================================================
// K1: in_proj, outputs split in half per block.
// grid (HW/64, 2, B), block 256.  smem ~64KB.  t1 stored fp16.
// =====================================================================
__global__ void __launch_bounds__(256) k1_inproj(const float* __restrict__ x,
                                                 const float* __restrict__ w) {
    extern __shared__ float sm1[];
    float* sw = sm1;              // sw[c*98 + olocal]
    float* sx = sm1 + 96*98;      // sx[c*68 + t]
    int b = blockIdx.z, oh = blockIdx.y;
    int pos0 = blockIdx.x * 64;
    int tid = threadIdx.x;

    for (int i = tid; i < 96*96; i += 256)
        sw[(i % 96)*98 + (i / 96)] = w[oh*96*96 + (i/96)*96 + (i%96)];
    for (int i = tid; i < CIN*64; i += 256) {
        int c = i >> 6, t = i & 63;
        sx[c*68 + t] = x[((size_t)b*CIN + c)*HWSZ + pos0 + t];
    }
    __syncthreads();

    int tg = tid & 15, og = tid >> 4;
    int t0 = tg * 4, o0 = og * 6;
    unsigned long long acc[3][4];
    #pragma unroll
    for (int i = 0; i < 3; i++)
        #pragma unroll
        for (int j = 0; j < 4; j++) acc[i][j] = 0ull;

    for (int c = 0; c < CIN; ++c) {
        float4 xv = *(const float4*)&sx[c*68 + t0];
        unsigned long long xp[4] = {pk2(xv.x, xv.x), pk2(xv.y, xv.y),
                                    pk2(xv.z, xv.z), pk2(xv.w, xv.w)};
        const float* wrow = &sw[c*98 + o0];
        #pragma unroll
        for (int i = 0; i < 3; ++i) {
            unsigned long long wp = *(const unsigned long long*)&wrow[2*i];
            #pragma unroll
            for (int t = 0; t < 4; ++t) FMA2(acc[i][t], wp, xp[t]);
        }
    }
    #pragma unroll
    for (int i = 0; i < 3; ++i) {
        float lo[4], hi[4];
        #pragma unroll
        for (int t = 0; t < 4; ++t) upk2(lo[t], hi[t], acc[i][t]);
        size_t r0 = ((size_t)b*DI + oh*96 + o0 + 2*i)*HWSZ + pos0 + t0;
        *(__half2*)&g_t1[r0]            = __floats2half2_rn(lo[0], lo[1]);
        *(__half2*)&g_t1[r0 + 2]        = __floats2half2_rn(lo[2], lo[3]);
        *(__half2*)&g_t1[r0 + HWSZ]     = __floats2half2_rn(hi[0], hi[1]);
        *(__half2*)&g_t1[r0 + HWSZ + 2] = __floats2half2_rn(hi[2], hi[3]);
    }
}

// =====================================================================
// K2 (fused): depthwise 3x3 conv + bias + silu -> xft (transposed, fp16)
//             AND x_dbl projection (xpw staged in dead s_in; xdbl fp16).
// grid (W/32, H, B), block 256.  smem ~111KB, 2 blocks/SM.
// =====================================================================
__global__ void __launch_bounds__(256) k2_conv(const float* __restrict__ cw,
                                               const float* __restrict__ cb,
                                               const float* __restrict__ xpw) {
    extern __shared__ float sm2[];
    float* s_in  = sm2;                 // [rc*193 + d], rc = r*34+c
    float* s_out = sm2 + 102*193;       // [w*193 + d]
    float* s_w9  = sm2 + 102*193 + 32*193;   // [d*9+i]
    float* s_b   = s_w9 + DI*9;              // [d]
    float* s_xw  = s_in;                      // reused after conv: [d*36 + kc]
    int b = blockIdx.z, h = blockIdx.y, w0 = blockIdx.x * 32;
    int tid = threadIdx.x;

    for (int i = tid; i < DI*9; i += 256) s_w9[i] = cw[i];
    for (int i = tid; i < DI; i += 256) s_b[i] = cb[i];
    for (int i = tid; i < 3*34*DI; i += 256) {
        int dd = i / 102, rc = i % 102;
        int r = rc / 34, c = rc % 34;
        int hh = h + r - 1, ww = w0 + c - 1;
        float v = 0.f;
        if (hh >= 0 && hh < HH && ww >= 0 && ww < WW)
            v = __half2float(g_t1[((size_t)b*DI + dd)*HWSZ + hh*WW + ww]);
        s_in[rc*193 + dd] = v;
    }
    __syncthreads();

    int w = tid & 31, dg = tid >> 5;
    #pragma unroll 4
    for (int dd = 0; dd < 24; ++dd) {
        int d = dg*24 + dd;
        float sum = s_b[d];
        #pragma unroll
        for (int r = 0; r < 3; ++r)
            #pragma unroll
            for (int dc = 0; dc < 3; ++dc)
                sum += s_w9[d*9 + r*3 + dc] * s_in[(r*34 + w + dc)*193 + d];
        s_out[w*193 + d] = sum / (1.f + __expf(-sum));
    }
    __syncthreads();        // s_out complete; s_in now dead

    for (int i = tid; i < 32*DI; i += 256) {
        int ww = i / DI, d = i % DI;
        g_xft[((size_t)b*HWSZ + h*WW + w0 + ww)*DI + d] = __float2half_rn(s_out[ww*193 + d]);
    }
    for (int i = tid; i < 32*DI; i += 256) {
        int kc = i / DI, d2 = i % DI;
        s_xw[d2*36 + kc] = xpw[i];
    }
    __syncthreads();

    int og = tid >> 5;                  // 8 groups of 4 kc
    unsigned long long acc2[2] = {0ull, 0ull};
    for (int d = 0; d < DI; ++d) {
        float s = s_out[w*193 + d];
        unsigned long long sp = pk2(s, s);
        const float* xw = &s_xw[d*36 + og*4];
        unsigned long long w01 = *(const unsigned long long*)&xw[0];
        unsigned long long w23 = *(const unsigned long long*)&xw[2];
        FMA2(acc2[0], w01, sp);
        FMA2(acc2[1], w23, sp);
    }
    float r0, r1, r2, r3;
    upk2(r0, r1, acc2[0]);
    upk2(r2, r3, acc2[1]);
    size_t pos = (size_t)b*HWSZ + h*WW + w0 + w;
    __half2 h01 = __floats2half2_rn(r0, r1);
    __half2 h23 = __floats2half2_rn(r2, r3);
    uint2 pv;
    pv.x = *(unsigned*)&h01;
    pv.y = *(unsigned*)&h23;
    *(uint2*)&g_xdbl[pos*32 + og*4] = pv;
}

// =====================================================================
// K4: selective scan (topology frozen).  xdbl fp16: one uint4 per element.
// block 256 = 32 slots x 8 d; warp w scans channel d=w via shfl.
// grid (DI/8=24, K, B) = 384 blocks.  ys fp16, u fp16.
// =====================================================================
__global__ void __launch_bounds__(256, 4) k4_scan(const float* __restrict__ dtw,
                        const float* __restrict__ dtb,
                        const float* __restrict__ Alog,
                        const float* __restrict__ Dsv,
                        const int*   __restrict__ scan) {
    __shared__ float s_pa[32*9], s_pb[32*9], s_hs[32*9];
    int b = blockIdx.z, k = blockIdx.y, dg = blockIdx.x;
    int tid = threadIdx.x;
    int dsub = tid & 7, slot = tid >> 3;
    int d = dg*8 + dsub;
    int kd = k*DI + d;
    int lane = tid & 31, wid = tid >> 5;

    float w0 = dtw[kd*6+0], w1 = dtw[kd*6+1], w2 = dtw[kd*6+2];
    float w3 = dtw[kd*6+3], w4 = dtw[kd*6+4], w5 = dtw[kd*6+5];
    float bias = dtb[kd];
    float Aval = -__expf(Alog[kd]);
    float Dval = Dsv[kd];
    const int*    sc     = scan + k*HWSZ;
    const __half* xdbl_b = g_xdbl + (size_t)b*HWSZ*32 + k*8;
    const __half* xft_b  = g_xft  + (size_t)b*HWSZ*DI + d;
    __half*       ys_b   = g_ys   + (size_t)b*HWSZ*(KDIR*DI) + k*DI + d;
    float hprev = 0.f;

    for (int ch = 0; ch < 64; ++ch) {
        int l0 = ch*256 + slot*8;
        int4 pA = *(const int4*)&sc[l0];
        int4 pB = *(const int4*)&sc[l0 + 4];
        int pos[8] = {pA.x, pA.y, pA.z, pA.w, pB.x, pB.y, pB.z, pB.w};

        float a[8], bu[8], Cv[8], du[8];
        #pragma unroll
        for (int j = 0; j < 8; ++j) {
            uint4 v = *(const uint4*)(xdbl_b + (size_t)pos[j]*32);
            const __half2* q = (const __half2*)&v;
            float2 d01 = __half22float2(q[0]);
            float2 d23 = __half22float2(q[1]);
            float2 d45 = __half22float2(q[2]);
            float2 BC  = __half22float2(q[3]);
            float u = __half2float(xft_b[(size_t)pos[j]*DI]);
            float dt = bias + w0*d01.x + w1*d01.y + w2*d23.x + w3*d23.y + w4*d45.x + w5*d45.y;
            float delta = fmaxf(dt, 0.f) + __logf(1.f + __expf(-fabsf(dt)));
            a[j]  = __expf(delta * Aval);
            bu[j] = delta * BC.x * u;
            Cv[j] = BC.y;
            du[j] = Dval * u;
        }
        float aP = a[0], bP = bu[0];
        #pragma unroll
        for (int j = 1; j < 8; ++j) { bP = a[j]*bP + bu[j]; aP *= a[j]; }
        s_pa[slot*9 + dsub] = aP;
        s_pb[slot*9 + dsub] = bP;
        __syncthreads();

        {   // warp `wid` scans the 32 slot-partials of channel dsub==wid
            float ai = s_pa[lane*9 + wid];
            float bi = s_pb[lane*9 + wid];
            #pragma unroll
            for (int off = 1; off < 32; off <<= 1) {
                float pa = __shfl_up_sync(0xffffffffu, ai, off);
                float pb = __shfl_up_sync(0xffffffffu, bi, off);
                if (lane >= off) { bi = ai*pb + bi; ai *= pa; }
            }
            float aE = __shfl_up_sync(0xffffffffu, ai, 1);
            float bE = __shfl_up_sync(0xffffffffu, bi, 1);
            if (lane == 0) { aE = 1.f; bE = 0.f; }
            s_hs[lane*9 + wid] = aE*hprev + bE;
            float aI = __shfl_sync(0xffffffffu, ai, 31);
            float bI = __shfl_sync(0xffffffffu, bi, 31);
            hprev = aI*hprev + bI;
        }
        __syncthreads();

        float h = s_hs[slot*9 + dsub];
        #pragma unroll
        for (int j = 0; j < 8; ++j) {
            h = a[j]*h + bu[j];
            ys_b[(size_t)pos[j]*(KDIR*DI)] = __float2half_rn(Cv[j]*h + du[j]);
        }
    }
}

// =====================================================================
// K5a: streaming sum over K + gelu, 16B loads/stores.
// block 192 = 24 q x 8 po; grid B*HW/8.  Thread q handles 8 d.
// =====================================================================
__global__ void __launch_bounds__(192) k5a_gelu(void) {
    int tid = threadIdx.x;
    int q = tid % 24, po = tid / 24;
    size_t pg = (size_t)blockIdx.x*8 + po;
    const uint4* src = (const uint4*)(g_ys + pg*(KDIR*DI));   // 16B = 8 halfs
    float acc[8];
    {
        uint4 v = src[q];
        const __half2* h2 = (const __half2*)&v;
        #pragma unroll
        for (int p = 0; p < 4; ++p) {
            float2 f = __half22float2(h2[p]);
            acc[2*p] = f.x; acc[2*p+1] = f.y;
        }
    }
    #pragma unroll
    for (int kk = 1; kk < KDIR; ++kk) {
        uint4 v = src[kk*24 + q];
        const __half2* h2 = (const __half2*)&v;
        #pragma unroll
        for (int p = 0; p < 4; ++p) {
            float2 f = __half22float2(h2[p]);
            acc[2*p] += f.x; acc[2*p+1] += f.y;
        }
    }
    uint4 outv;
    __half2* oh2 = (__half2*)&outv;
    #pragma unroll
    for (int p = 0; p < 4; ++p) {
        float r0 = acc[2*p], r1 = acc[2*p+1];
        float z0 = 0.7978845608f * (r0 + 0.044715f*r0*r0*r0);
        float z1 = 0.7978845608f * (r1 + 0.044715f*r1*r1*r1);
        float t0 = 2.f / (1.f + __expf(-2.f*z0)) - 1.f;
        float t1 = 2.f / (1.f + __expf(-2.f*z1)) - 1.f;
        oh2[p] = __floats2half2_rn(0.5f*r0*(1.f + t0), 0.5f*r1*(1.f + t1));
    }
    ((uint4*)(g_g + pg*DI))[q] = outv;
}

// =====================================================================
// K5b: out_proj GEMM, outputs split 2-way.  grid (HW/64, 2, B), block 256
// =====================================================================
__global__ void __launch_bounds__(256) k5b_out(const float* __restrict__ ow,
                                               float* __restrict__ out) {
    extern __shared__ float sm5[];
    float* sw = sm5;              // sw[d*50 + ol]
    float* sg = sm5 + DI*50;      // sg[d*70 + t]
    int b = blockIdx.z, oq = blockIdx.y;
    int pos0 = blockIdx.x * 64, tid = threadIdx.x;

    for (int i = tid; i < 48*DI; i += 256)
        sw[(i % DI)*50 + (i / DI)] = ow[oq*48*DI + i];
    int lane = tid & 31, wid = tid >> 5;
    #pragma unroll
    for (int pp = 0; pp < 8; ++pp) {
        int po = wid*8 + pp;
        const __half* src = g_g + ((size_t)b*HWSZ + pos0 + po)*DI;
        #pragma unroll
        for (int i = 0; i < 6; ++i)
            sg[(lane + 32*i)*70 + po] = __half2float(src[lane + 32*i]);
    }
    __syncthreads();

    int tg = tid & 31, og = tid >> 5;
    int t0 = tg*2, o0 = og*6;
    unsigned long long acc[3][2];
    #pragma unroll
    for (int i = 0; i < 3; i++) { acc[i][0] = 0ull; acc[i][1] = 0ull; }

    for (int d = 0; d < DI; ++d) {
        float2 gv = *(const float2*)&sg[d*70 + t0];
        unsigned long long gp[2] = {pk2(gv.x, gv.x), pk2(gv.y, gv.y)};
        const float* wrow = &sw[d*50 + o0];
        #pragma unroll
        for (int i = 0; i < 3; ++i) {
            unsigned long long wp = *(const unsigned long long*)&wrow[2*i];
            FMA2(acc[i][0], wp, gp[0]);
            FMA2(acc[i][1], wp, gp[1]);
        }
    }
    #pragma unroll
    for (int i = 0; i < 3; ++i) {
        float lo0, hi0, lo1, hi1;
        upk2(lo0, hi0, acc[i][0]);
        upk2(lo1, hi1, acc[i][1]);
        size_t r0 = ((size_t)b*CIN + oq*48 + o0 + 2*i)*HWSZ + pos0 + t0;
        *(float2*)&out[r0]        = make_float2(lo0, lo1);
        *(float2*)&out[r0 + HWSZ] = make_float2(hi0, hi1);
    }
}

// =====================================================================
extern "C" void kernel_launch(void* const* d_in, const int* in_sizes, int n_in,
                              void* d_out, int out_size) {
    const float* x    = (const float*)d_in[0];
    const int*   scan = (const int*)d_in[1];
    const float* ipw  = (const float*)d_in[3];
    const float* cw   = (const float*)d_in[4];
    const float* cb   = (const float*)d_in[5];
    const float* xpw  = (const float*)d_in[6];
    const float* dtw  = (const float*)d_in[7];
    const float* dtb  = (const float*)d_in[8];
    const float* Alog = (const float*)d_in[9];
    const float* Dsv  = (const float*)d_in[10];
    const float* ow   = (const float*)d_in[11];
    float* out = (float*)d_out;

    const int SM1 = (96*98 + 96*68) * 4;
    const int SM2 = (102*193 + 32*193 + DI*9 + DI) * 4;
    const int SM5 = (DI*50 + DI*70) * 4;
    cudaFuncSetAttribute(k1_inproj, cudaFuncAttributeMaxDynamicSharedMemorySize, SM1);
    cudaFuncSetAttribute(k2_conv,   cudaFuncAttributeMaxDynamicSharedMemorySize, SM2);
    cudaFuncSetAttribute(k5b_out,   cudaFuncAttributeMaxDynamicSharedMemorySize, SM5);

    dim3 g1(HWSZ/64, 2, BATCH);
    k1_inproj<<<g1, 256, SM1>>>(x, ipw);
    dim3 g2(WW/32, HH, BATCH);
    k2_conv<<<g2, 256, SM2>>>(cw, cb, xpw);
    dim3 g4(DI/8, KDIR, BATCH);
    k4_scan<<<g4, 256>>>(dtw, dtb, Alog, Dsv, scan);
    k5a_gelu<<<BATCH*HWSZ/8, 192>>>();
    dim3 g5(HWSZ/64, 2, BATCH);
    k5b_out<<<g5, 256, SM5>>>(ow, out);
}